// round 1
// baseline (speedup 1.0000x reference)
#include <cuda_runtime.h>
#include <math.h>
#include <stdint.h>

// ---------------------------------------------------------------------------
// chanFSM: LN -> GEMM1(+gelu) -> GEMM2(+bias,gelu) -> GEMM3(+gelu) -> GEMV ->
// sigmoid -> STE threshold -> broadcast multiply.
// All GEMMs in fp32 SIMT (precision required: mask threshold at logit==0).
// ---------------------------------------------------------------------------

namespace {

constexpr int ROWS = 65536;   // B*N = 32*2048
constexpr int C    = 1024;
constexpr int C2   = 512;
constexpr int C4   = 256;

// Scratch (static device globals: no allocation allowed in kernel_launch)
__device__ __align__(128) float g_WL[(size_t)C * C2];   // ln_scale-folded W_L
__device__ __align__(128) float g_s[C2];                // colsum of g_WL
__device__ __align__(128) float g_c1[C2];               // ln_bias @ W_L
__device__ __align__(128) float g_c2[C2];               // noise @ W_l1[512:,:]
__device__ __align__(128) float g_mu[ROWS];
__device__ __align__(128) float g_rstd[ROWS];
__device__ __align__(128) float g_h1[(size_t)ROWS * C2];
__device__ __align__(128) float g_h2[(size_t)ROWS * C2];
__device__ __align__(128) float g_h3[(size_t)ROWS * C4];
__device__ __align__(128) float g_curr[ROWS];

__device__ __forceinline__ float gelu_exact(float x) {
    return 0.5f * x * (1.0f + erff(x * 0.70710678118654752440f));
}

// ---------------------------------------------------------------------------
// prep: fold ln_scale into W_L, compute column sums, ln_bias@W_L, noise bias.
// One thread per output column j (512 threads total).
// ---------------------------------------------------------------------------
__global__ void prep_kernel(const float* __restrict__ W_L,
                            const float* __restrict__ ln_scale,
                            const float* __restrict__ ln_bias,
                            const float* __restrict__ W_l1,
                            const float* __restrict__ noise) {
    int j = blockIdx.x * blockDim.x + threadIdx.x;
    if (j >= C2) return;
    float s = 0.0f, c1 = 0.0f;
    for (int k = 0; k < C; k++) {
        float w  = W_L[(size_t)k * C2 + j];
        float wp = ln_scale[k] * w;
        g_WL[(size_t)k * C2 + j] = wp;
        s  += wp;
        c1 += ln_bias[k] * w;
    }
    float c2 = 0.0f;
    for (int k = 0; k < C2; k++) {
        c2 += noise[k] * W_l1[(size_t)(C2 + k) * C2 + j];
    }
    g_s[j]  = s;
    g_c1[j] = c1;
    g_c2[j] = c2;
}

// ---------------------------------------------------------------------------
// Per-row mean / rstd (LayerNorm stats). One block (256 threads) per row.
// ---------------------------------------------------------------------------
__global__ void stats_kernel(const float* __restrict__ x) {
    int row = blockIdx.x;
    const float4* xr = reinterpret_cast<const float4*>(x + (size_t)row * C);
    float4 v = xr[threadIdx.x];
    float s = v.x + v.y + v.z + v.w;
    float q = v.x * v.x + v.y * v.y + v.z * v.z + v.w * v.w;
    #pragma unroll
    for (int o = 16; o > 0; o >>= 1) {
        s += __shfl_down_sync(0xffffffffu, s, o);
        q += __shfl_down_sync(0xffffffffu, q, o);
    }
    __shared__ float ss[8], sq[8];
    int lane = threadIdx.x & 31, w = threadIdx.x >> 5;
    if (lane == 0) { ss[w] = s; sq[w] = q; }
    __syncthreads();
    if (threadIdx.x == 0) {
        float S = 0.0f, Q = 0.0f;
        #pragma unroll
        for (int i = 0; i < 8; i++) { S += ss[i]; Q += sq[i]; }
        float mu  = S * (1.0f / C);
        float var = Q * (1.0f / C) - mu * mu;
        g_mu[row]   = mu;
        g_rstd[row] = 1.0f / sqrtf(var + 1e-5f);
    }
}

// ---------------------------------------------------------------------------
// SGEMM 128x128x8, 8x8 per-thread microtile, 256 threads.
// EPI 1: LN-fused  out = gelu(rstd*(acc - mu*colS) + colB)
// EPI 2: bias      out = gelu(acc + colB)
// EPI 3: plain     out = gelu(acc)
// M,N,K all divisible by tile dims for our shapes -> no bounds checks.
// ---------------------------------------------------------------------------
#define GBM 128
#define GBN 128
#define GBK 8
#define GTM 8
#define GTN 8

template <int EPI>
__global__ __launch_bounds__(256, 2) void sgemm_kernel(
    const float* __restrict__ A, const float* __restrict__ B,
    float* __restrict__ Cm, int M, int N, int K,
    const float* __restrict__ mu, const float* __restrict__ rstd,
    const float* __restrict__ colS, const float* __restrict__ colB) {

    __shared__ float As[GBK][GBM];
    __shared__ float Bs[GBK][GBN];

    const int tid = threadIdx.x;
    const int bm = blockIdx.y, bn = blockIdx.x;
    const int tRow = tid / (GBN / GTN);   // 0..15
    const int tCol = tid % (GBN / GTN);   // 0..15

    const float* Ablk = A + (size_t)bm * GBM * K;
    const float* Bblk = B + (size_t)bn * GBN;

    const int aRow = tid >> 1;            // 0..127
    const int aCol = (tid & 1) * 4;       // 0 or 4
    const int bRow = tid >> 5;            // 0..7
    const int bCol = (tid & 31) * 4;      // 0..124

    float acc[GTM][GTN] = {};

    for (int k0 = 0; k0 < K; k0 += GBK) {
        float4 av = *reinterpret_cast<const float4*>(Ablk + (size_t)aRow * K + k0 + aCol);
        float4 bv = *reinterpret_cast<const float4*>(Bblk + (size_t)(k0 + bRow) * N + bCol);
        __syncthreads();   // previous iteration's compute done before overwrite
        As[aCol + 0][aRow] = av.x;
        As[aCol + 1][aRow] = av.y;
        As[aCol + 2][aRow] = av.z;
        As[aCol + 3][aRow] = av.w;
        *reinterpret_cast<float4*>(&Bs[bRow][bCol]) = bv;
        __syncthreads();

        #pragma unroll
        for (int k = 0; k < GBK; k++) {
            float rm[GTM], rn[GTN];
            *reinterpret_cast<float4*>(&rm[0]) = *reinterpret_cast<const float4*>(&As[k][tRow * GTM]);
            *reinterpret_cast<float4*>(&rm[4]) = *reinterpret_cast<const float4*>(&As[k][tRow * GTM + 4]);
            *reinterpret_cast<float4*>(&rn[0]) = *reinterpret_cast<const float4*>(&Bs[k][tCol * GTN]);
            *reinterpret_cast<float4*>(&rn[4]) = *reinterpret_cast<const float4*>(&Bs[k][tCol * GTN + 4]);
            #pragma unroll
            for (int i = 0; i < GTM; i++)
                #pragma unroll
                for (int j = 0; j < GTN; j++)
                    acc[i][j] = fmaf(rm[i], rn[j], acc[i][j]);
        }
    }

    // epilogue
    #pragma unroll
    for (int i = 0; i < GTM; i++) {
        const int m = bm * GBM + tRow * GTM + i;
        float r = 1.0f, muv = 0.0f;
        if (EPI == 1) { r = rstd[m]; muv = mu[m]; }
        float vals[GTN];
        #pragma unroll
        for (int j = 0; j < GTN; j++) {
            const int n = bn * GBN + tCol * GTN + j;
            float v = acc[i][j];
            if (EPI == 1)      v = r * (v - muv * colS[n]) + colB[n];
            else if (EPI == 2) v = v + colB[n];
            vals[j] = gelu_exact(v);
        }
        float* cp = Cm + (size_t)m * N + bn * GBN + tCol * GTN;
        *reinterpret_cast<float4*>(cp)     = make_float4(vals[0], vals[1], vals[2], vals[3]);
        *reinterpret_cast<float4*>(cp + 4) = make_float4(vals[4], vals[5], vals[6], vals[7]);
    }
}

// ---------------------------------------------------------------------------
// GEMV + sigmoid + STE threshold. One warp per row (256-wide dot).
// Writes mask (as float 0/1) and curr_m + 1e-10 into the output tail,
// plus g_curr for the final broadcast-multiply kernel.
// ---------------------------------------------------------------------------
__global__ void gemv_kernel(const float* __restrict__ h3,
                            const float* __restrict__ w3,
                            const float* __restrict__ prev,
                            float* __restrict__ out_mask,
                            float* __restrict__ out_cm) {
    int gwarp = (blockIdx.x * blockDim.x + threadIdx.x) >> 5;   // row
    int lane  = threadIdx.x & 31;
    const float4* hr = reinterpret_cast<const float4*>(h3 + (size_t)gwarp * C4);
    const float4* wr = reinterpret_cast<const float4*>(w3);
    float4 a0 = hr[lane * 2], a1 = hr[lane * 2 + 1];
    float4 b0 = wr[lane * 2], b1 = wr[lane * 2 + 1];
    float d = a0.x * b0.x + a0.y * b0.y + a0.z * b0.z + a0.w * b0.w
            + a1.x * b1.x + a1.y * b1.y + a1.z * b1.z + a1.w * b1.w;
    #pragma unroll
    for (int o = 16; o > 0; o >>= 1) d += __shfl_down_sync(0xffffffffu, d, o);
    if (lane == 0) {
        float prob = 1.0f / (1.0f + expf(-d));
        float t = prob * prev[gwarp];
        float cur = (t > 0.5f) ? 1.0f : 0.0f;
        g_curr[gwarp]   = cur;
        out_mask[gwarp] = cur;           // int mask stored as float 0/1
        out_cm[gwarp]   = cur + 1e-10f;
    }
}

// ---------------------------------------------------------------------------
// out[row, :] = input[row, :] * curr_m[row]   (float4 per thread)
// ---------------------------------------------------------------------------
__global__ void mul_kernel(const float* __restrict__ x, float* __restrict__ out) {
    size_t i = (size_t)blockIdx.x * blockDim.x + threadIdx.x;   // float4 index
    float m = g_curr[i >> 8];                                   // C/4 = 256 float4 per row
    float4 v = reinterpret_cast<const float4*>(x)[i];
    v.x *= m; v.y *= m; v.z *= m; v.w *= m;
    reinterpret_cast<float4*>(out)[i] = v;
}

}  // namespace

// ---------------------------------------------------------------------------
extern "C" void kernel_launch(void* const* d_in, const int* in_sizes, int n_in,
                              void* d_out, int out_size) {
    const float* input = (const float*)d_in[0];  // [32,2048,1024]
    const float* noise = (const float*)d_in[1];  // [1,1,512]
    const float* prev  = (const float*)d_in[2];  // [32,2048]
    const float* lns   = (const float*)d_in[3];  // [1024]
    const float* lnb   = (const float*)d_in[4];  // [1024]
    const float* W_L   = (const float*)d_in[5];  // [1024,512]
    const float* W_l1  = (const float*)d_in[6];  // [1024,512]
    const float* W_l2  = (const float*)d_in[7];  // [512,256]
    const float* W_l3  = (const float*)d_in[8];  // [256,1]

    float* out      = (float*)d_out;
    float* out_mask = out + (size_t)ROWS * C;
    float* out_cm   = out_mask + ROWS;

    float *p_WL, *p_s, *p_c1, *p_c2, *p_mu, *p_rstd, *p_h1, *p_h2, *p_h3;
    cudaGetSymbolAddress((void**)&p_WL,   g_WL);
    cudaGetSymbolAddress((void**)&p_s,    g_s);
    cudaGetSymbolAddress((void**)&p_c1,   g_c1);
    cudaGetSymbolAddress((void**)&p_c2,   g_c2);
    cudaGetSymbolAddress((void**)&p_mu,   g_mu);
    cudaGetSymbolAddress((void**)&p_rstd, g_rstd);
    cudaGetSymbolAddress((void**)&p_h1,   g_h1);
    cudaGetSymbolAddress((void**)&p_h2,   g_h2);
    cudaGetSymbolAddress((void**)&p_h3,   g_h3);

    // 1. fold weights / constant biases
    prep_kernel<<<8, 64>>>(W_L, lns, lnb, W_l1, noise);
    // 2. LN row stats
    stats_kernel<<<ROWS, 256>>>(input);
    // 3. GEMM1: gelu(LN(x) @ W_L')     [65536,1024]x[1024,512]
    {
        dim3 grid(C2 / GBN, ROWS / GBM);
        sgemm_kernel<1><<<grid, 256>>>(input, p_WL, p_h1, ROWS, C2, C,
                                       p_mu, p_rstd, p_s, p_c1);
    }
    // 4. GEMM2: gelu(h1 @ W_l1[:512] + c2)   [65536,512]x[512,512]
    {
        dim3 grid(C2 / GBN, ROWS / GBM);
        sgemm_kernel<2><<<grid, 256>>>(p_h1, W_l1, p_h2, ROWS, C2, C2,
                                       nullptr, nullptr, nullptr, p_c2);
    }
    // 5. GEMM3: gelu(h2 @ W_l2)        [65536,512]x[512,256]
    {
        dim3 grid(C4 / GBN, ROWS / GBM);
        sgemm_kernel<3><<<grid, 256>>>(p_h2, W_l2, p_h3, ROWS, C4, C2,
                                       nullptr, nullptr, nullptr, nullptr);
    }
    // 6. GEMV + sigmoid + STE threshold (writes mask + curr_m tail outputs)
    gemv_kernel<<<ROWS / 8, 256>>>(p_h3, W_l3, prev, out_mask, out_cm);
    // 7. out = input * curr_m[..., None]
    mul_kernel<<<(ROWS * (C / 4)) / 256, 256>>>(input, out);
}

// round 2
// speedup vs baseline: 1.0393x; 1.0393x over previous
#include <cuda_runtime.h>
#include <math.h>
#include <stdint.h>

// ---------------------------------------------------------------------------
// chanFSM: LN -> GEMM1(+gelu) -> GEMM2(+bias,gelu) -> GEMM3(+gelu) -> GEMV ->
// sigmoid -> STE threshold -> broadcast multiply.
// fp32 GEMMs using Blackwell packed fma.rn.f32x2 + double-buffered smem.
// Summation order per accumulator identical to round-1 kernel -> bit-identical.
// ---------------------------------------------------------------------------

namespace {

constexpr int ROWS = 65536;   // B*N = 32*2048
constexpr int C    = 1024;
constexpr int C2   = 512;
constexpr int C4   = 256;

// Scratch (static device globals: no allocation allowed in kernel_launch)
__device__ __align__(128) float g_WL[(size_t)C * C2];   // ln_scale-folded W_L
__device__ __align__(128) float g_s[C2];                // colsum of g_WL
__device__ __align__(128) float g_c1[C2];               // ln_bias @ W_L
__device__ __align__(128) float g_c2[C2];               // noise @ W_l1[512:,:]
__device__ __align__(128) float g_mu[ROWS];
__device__ __align__(128) float g_rstd[ROWS];
__device__ __align__(128) float g_h1[(size_t)ROWS * C2];
__device__ __align__(128) float g_h2[(size_t)ROWS * C2];
__device__ __align__(128) float g_h3[(size_t)ROWS * C4];
__device__ __align__(128) float g_curr[ROWS];

__device__ __forceinline__ float gelu_exact(float x) {
    return 0.5f * x * (1.0f + erff(x * 0.70710678118654752440f));
}

// Packed fp32x2 helpers (Blackwell dual-rate fp32 path; PTX-only).
__device__ __forceinline__ void ffma2(unsigned long long& d,
                                      unsigned long long a,
                                      unsigned long long b) {
    asm("fma.rn.f32x2 %0, %1, %2, %0;" : "+l"(d) : "l"(a), "l"(b));
}
__device__ __forceinline__ unsigned long long pack2(float x, float y) {
    unsigned long long r;
    asm("mov.b64 %0, {%1, %2};" : "=l"(r) : "f"(x), "f"(y));
    return r;
}
__device__ __forceinline__ void unpack2(unsigned long long v, float& x, float& y) {
    asm("mov.b64 {%0, %1}, %2;" : "=f"(x), "=f"(y) : "l"(v));
}

union F4U2 {
    float4 f;
    unsigned long long u[2];
};

// ---------------------------------------------------------------------------
// prep: fold ln_scale into W_L, compute column sums, ln_bias@W_L, noise bias.
// ---------------------------------------------------------------------------
__global__ void prep_kernel(const float* __restrict__ W_L,
                            const float* __restrict__ ln_scale,
                            const float* __restrict__ ln_bias,
                            const float* __restrict__ W_l1,
                            const float* __restrict__ noise) {
    int j = blockIdx.x * blockDim.x + threadIdx.x;
    if (j >= C2) return;
    float s = 0.0f, c1 = 0.0f;
    for (int k = 0; k < C; k++) {
        float w  = W_L[(size_t)k * C2 + j];
        float wp = ln_scale[k] * w;
        g_WL[(size_t)k * C2 + j] = wp;
        s  += wp;
        c1 += ln_bias[k] * w;
    }
    float c2 = 0.0f;
    for (int k = 0; k < C2; k++) {
        c2 += noise[k] * W_l1[(size_t)(C2 + k) * C2 + j];
    }
    g_s[j]  = s;
    g_c1[j] = c1;
    g_c2[j] = c2;
}

// ---------------------------------------------------------------------------
// Per-row mean / rstd (LayerNorm stats). One block (256 threads) per row.
// ---------------------------------------------------------------------------
__global__ void stats_kernel(const float* __restrict__ x) {
    int row = blockIdx.x;
    const float4* xr = reinterpret_cast<const float4*>(x + (size_t)row * C);
    float4 v = xr[threadIdx.x];
    float s = v.x + v.y + v.z + v.w;
    float q = v.x * v.x + v.y * v.y + v.z * v.z + v.w * v.w;
    #pragma unroll
    for (int o = 16; o > 0; o >>= 1) {
        s += __shfl_down_sync(0xffffffffu, s, o);
        q += __shfl_down_sync(0xffffffffu, q, o);
    }
    __shared__ float ss[8], sq[8];
    int lane = threadIdx.x & 31, w = threadIdx.x >> 5;
    if (lane == 0) { ss[w] = s; sq[w] = q; }
    __syncthreads();
    if (threadIdx.x == 0) {
        float S = 0.0f, Q = 0.0f;
        #pragma unroll
        for (int i = 0; i < 8; i++) { S += ss[i]; Q += sq[i]; }
        float mu  = S * (1.0f / C);
        float var = Q * (1.0f / C) - mu * mu;
        g_mu[row]   = mu;
        g_rstd[row] = 1.0f / sqrtf(var + 1e-5f);
    }
}

// ---------------------------------------------------------------------------
// SGEMM 128x128x16, 8x8 per-thread microtile (paired along m as f32x2),
// 256 threads, double-buffered smem, one __syncthreads per 16 k-steps.
// EPI 1: LN-fused  out = gelu(rstd*(acc - mu*colS) + colB)
// EPI 2: bias      out = gelu(acc + colB)
// EPI 3: plain     out = gelu(acc)
// Shapes always divide tile dims -> no bounds checks.
// ---------------------------------------------------------------------------
#define GBM 128
#define GBN 128
#define GBK 16
#define GTM 8
#define GTN 8

template <int EPI>
__global__ __launch_bounds__(256, 2) void sgemm_kernel(
    const float* __restrict__ A, const float* __restrict__ B,
    float* __restrict__ Cm, int M, int N, int K,
    const float* __restrict__ mu, const float* __restrict__ rstd,
    const float* __restrict__ colS, const float* __restrict__ colB) {

    __shared__ float As[2][GBK][GBM];
    __shared__ float Bs[2][GBK][GBN];

    const int tid = threadIdx.x;
    const int bm = blockIdx.y, bn = blockIdx.x;
    const int tRow = tid / (GBN / GTN);   // 0..15
    const int tCol = tid % (GBN / GTN);   // 0..15

    const float* Ablk = A + (size_t)bm * GBM * K;
    const float* Bblk = B + (size_t)bn * GBN;

    // A tile: 128 x 16 -> 512 float4, 2 per thread (same row, cols aCol..aCol+7)
    const int aRow = tid >> 1;             // 0..127
    const int aCol = (tid & 1) * 8;        // 0 or 8
    // B tile: 16 x 128 -> 512 float4, 2 per thread (same row, cols bCol..bCol+7)
    const int bRow = tid >> 4;             // 0..15
    const int bCol = (tid & 15) * 8;       // 0..120

    const int nIter = K / GBK;

    // acc pairs along m: acc2[p][j] = (acc[2p][j], acc[2p+1][j])
    unsigned long long acc2[GTM / 2][GTN];
    #pragma unroll
    for (int p = 0; p < GTM / 2; p++)
        #pragma unroll
        for (int j = 0; j < GTN; j++) acc2[p][j] = 0ull;

    // ---- stage 0 load ----
    {
        float4 a0 = *reinterpret_cast<const float4*>(Ablk + (size_t)aRow * K + aCol);
        float4 a1 = *reinterpret_cast<const float4*>(Ablk + (size_t)aRow * K + aCol + 4);
        float4 b0 = *reinterpret_cast<const float4*>(Bblk + (size_t)bRow * N + bCol);
        float4 b1 = *reinterpret_cast<const float4*>(Bblk + (size_t)bRow * N + bCol + 4);
        As[0][aCol + 0][aRow] = a0.x; As[0][aCol + 1][aRow] = a0.y;
        As[0][aCol + 2][aRow] = a0.z; As[0][aCol + 3][aRow] = a0.w;
        As[0][aCol + 4][aRow] = a1.x; As[0][aCol + 5][aRow] = a1.y;
        As[0][aCol + 6][aRow] = a1.z; As[0][aCol + 7][aRow] = a1.w;
        *reinterpret_cast<float4*>(&Bs[0][bRow][bCol])     = b0;
        *reinterpret_cast<float4*>(&Bs[0][bRow][bCol + 4]) = b1;
    }
    __syncthreads();

    for (int kt = 0; kt < nIter; kt++) {
        const int cur = kt & 1;
        float4 a0, a1, b0, b1;
        const bool more = (kt + 1 < nIter);
        if (more) {
            const int k0 = (kt + 1) * GBK;
            a0 = *reinterpret_cast<const float4*>(Ablk + (size_t)aRow * K + k0 + aCol);
            a1 = *reinterpret_cast<const float4*>(Ablk + (size_t)aRow * K + k0 + aCol + 4);
            b0 = *reinterpret_cast<const float4*>(Bblk + (size_t)(k0 + bRow) * N + bCol);
            b1 = *reinterpret_cast<const float4*>(Bblk + (size_t)(k0 + bRow) * N + bCol + 4);
        }

        #pragma unroll
        for (int k = 0; k < GBK; k++) {
            F4U2 am0, am1;
            am0.f = *reinterpret_cast<const float4*>(&As[cur][k][tRow * GTM]);
            am1.f = *reinterpret_cast<const float4*>(&As[cur][k][tRow * GTM + 4]);
            float4 r0 = *reinterpret_cast<const float4*>(&Bs[cur][k][tCol * GTN]);
            float4 r1 = *reinterpret_cast<const float4*>(&Bs[cur][k][tCol * GTN + 4]);
            unsigned long long bb[GTN];
            bb[0] = pack2(r0.x, r0.x); bb[1] = pack2(r0.y, r0.y);
            bb[2] = pack2(r0.z, r0.z); bb[3] = pack2(r0.w, r0.w);
            bb[4] = pack2(r1.x, r1.x); bb[5] = pack2(r1.y, r1.y);
            bb[6] = pack2(r1.z, r1.z); bb[7] = pack2(r1.w, r1.w);
            unsigned long long am[4] = {am0.u[0], am0.u[1], am1.u[0], am1.u[1]};
            #pragma unroll
            for (int p = 0; p < GTM / 2; p++)
                #pragma unroll
                for (int j = 0; j < GTN; j++)
                    ffma2(acc2[p][j], am[p], bb[j]);
        }

        if (more) {
            const int nxt = cur ^ 1;
            As[nxt][aCol + 0][aRow] = a0.x; As[nxt][aCol + 1][aRow] = a0.y;
            As[nxt][aCol + 2][aRow] = a0.z; As[nxt][aCol + 3][aRow] = a0.w;
            As[nxt][aCol + 4][aRow] = a1.x; As[nxt][aCol + 5][aRow] = a1.y;
            As[nxt][aCol + 6][aRow] = a1.z; As[nxt][aCol + 7][aRow] = a1.w;
            *reinterpret_cast<float4*>(&Bs[nxt][bRow][bCol])     = b0;
            *reinterpret_cast<float4*>(&Bs[nxt][bRow][bCol + 4]) = b1;
        }
        __syncthreads();
    }

    // ---- epilogue ----
    #pragma unroll
    for (int p = 0; p < GTM / 2; p++) {
        float accA[GTN], accB[GTN];     // rows 2p and 2p+1
        #pragma unroll
        for (int j = 0; j < GTN; j++) unpack2(acc2[p][j], accA[j], accB[j]);

        #pragma unroll
        for (int half = 0; half < 2; half++) {
            const float* accv = half ? accB : accA;
            const int m = bm * GBM + tRow * GTM + 2 * p + half;
            float r = 1.0f, muv = 0.0f;
            if (EPI == 1) { r = rstd[m]; muv = mu[m]; }
            float vals[GTN];
            #pragma unroll
            for (int j = 0; j < GTN; j++) {
                const int n = bn * GBN + tCol * GTN + j;
                float v = accv[j];
                if (EPI == 1)      v = r * (v - muv * colS[n]) + colB[n];
                else if (EPI == 2) v = v + colB[n];
                vals[j] = gelu_exact(v);
            }
            float* cp = Cm + (size_t)m * N + bn * GBN + tCol * GTN;
            *reinterpret_cast<float4*>(cp)     = make_float4(vals[0], vals[1], vals[2], vals[3]);
            *reinterpret_cast<float4*>(cp + 4) = make_float4(vals[4], vals[5], vals[6], vals[7]);
        }
    }
}

// ---------------------------------------------------------------------------
// GEMV + sigmoid + STE threshold. One warp per row (256-wide dot).
// ---------------------------------------------------------------------------
__global__ void gemv_kernel(const float* __restrict__ h3,
                            const float* __restrict__ w3,
                            const float* __restrict__ prev,
                            float* __restrict__ out_mask,
                            float* __restrict__ out_cm) {
    int gwarp = (blockIdx.x * blockDim.x + threadIdx.x) >> 5;   // row
    int lane  = threadIdx.x & 31;
    const float4* hr = reinterpret_cast<const float4*>(h3 + (size_t)gwarp * C4);
    const float4* wr = reinterpret_cast<const float4*>(w3);
    float4 a0 = hr[lane * 2], a1 = hr[lane * 2 + 1];
    float4 b0 = wr[lane * 2], b1 = wr[lane * 2 + 1];
    float d = a0.x * b0.x + a0.y * b0.y + a0.z * b0.z + a0.w * b0.w
            + a1.x * b1.x + a1.y * b1.y + a1.z * b1.z + a1.w * b1.w;
    #pragma unroll
    for (int o = 16; o > 0; o >>= 1) d += __shfl_down_sync(0xffffffffu, d, o);
    if (lane == 0) {
        float prob = 1.0f / (1.0f + expf(-d));
        float t = prob * prev[gwarp];
        float cur = (t > 0.5f) ? 1.0f : 0.0f;
        g_curr[gwarp]   = cur;
        out_mask[gwarp] = cur;           // int mask stored as float 0/1
        out_cm[gwarp]   = cur + 1e-10f;
    }
}

// ---------------------------------------------------------------------------
// out[row, :] = input[row, :] * curr_m[row]   (float4 per thread)
// ---------------------------------------------------------------------------
__global__ void mul_kernel(const float* __restrict__ x, float* __restrict__ out) {
    size_t i = (size_t)blockIdx.x * blockDim.x + threadIdx.x;   // float4 index
    float m = g_curr[i >> 8];                                   // 256 float4 per row
    float4 v = reinterpret_cast<const float4*>(x)[i];
    v.x *= m; v.y *= m; v.z *= m; v.w *= m;
    reinterpret_cast<float4*>(out)[i] = v;
}

}  // namespace

// ---------------------------------------------------------------------------
extern "C" void kernel_launch(void* const* d_in, const int* in_sizes, int n_in,
                              void* d_out, int out_size) {
    const float* input = (const float*)d_in[0];  // [32,2048,1024]
    const float* noise = (const float*)d_in[1];  // [1,1,512]
    const float* prev  = (const float*)d_in[2];  // [32,2048]
    const float* lns   = (const float*)d_in[3];  // [1024]
    const float* lnb   = (const float*)d_in[4];  // [1024]
    const float* W_L   = (const float*)d_in[5];  // [1024,512]
    const float* W_l1  = (const float*)d_in[6];  // [1024,512]
    const float* W_l2  = (const float*)d_in[7];  // [512,256]
    const float* W_l3  = (const float*)d_in[8];  // [256,1]

    float* out      = (float*)d_out;
    float* out_mask = out + (size_t)ROWS * C;
    float* out_cm   = out_mask + ROWS;

    float *p_WL, *p_s, *p_c1, *p_c2, *p_mu, *p_rstd, *p_h1, *p_h2, *p_h3;
    cudaGetSymbolAddress((void**)&p_WL,   g_WL);
    cudaGetSymbolAddress((void**)&p_s,    g_s);
    cudaGetSymbolAddress((void**)&p_c1,   g_c1);
    cudaGetSymbolAddress((void**)&p_c2,   g_c2);
    cudaGetSymbolAddress((void**)&p_mu,   g_mu);
    cudaGetSymbolAddress((void**)&p_rstd, g_rstd);
    cudaGetSymbolAddress((void**)&p_h1,   g_h1);
    cudaGetSymbolAddress((void**)&p_h2,   g_h2);
    cudaGetSymbolAddress((void**)&p_h3,   g_h3);

    // 1. fold weights / constant biases
    prep_kernel<<<8, 64>>>(W_L, lns, lnb, W_l1, noise);
    // 2. LN row stats
    stats_kernel<<<ROWS, 256>>>(input);
    // 3. GEMM1: gelu(LN(x) @ W_L')     [65536,1024]x[1024,512]
    {
        dim3 grid(C2 / GBN, ROWS / GBM);
        sgemm_kernel<1><<<grid, 256>>>(input, p_WL, p_h1, ROWS, C2, C,
                                       p_mu, p_rstd, p_s, p_c1);
    }
    // 4. GEMM2: gelu(h1 @ W_l1[:512] + c2)   [65536,512]x[512,512]
    {
        dim3 grid(C2 / GBN, ROWS / GBM);
        sgemm_kernel<2><<<grid, 256>>>(p_h1, W_l1, p_h2, ROWS, C2, C2,
                                       nullptr, nullptr, nullptr, p_c2);
    }
    // 5. GEMM3: gelu(h2 @ W_l2)        [65536,512]x[512,256]
    {
        dim3 grid(C4 / GBN, ROWS / GBM);
        sgemm_kernel<3><<<grid, 256>>>(p_h2, W_l2, p_h3, ROWS, C4, C2,
                                       nullptr, nullptr, nullptr, nullptr);
    }
    // 6. GEMV + sigmoid + STE threshold (writes mask + curr_m tail outputs)
    gemv_kernel<<<ROWS / 8, 256>>>(p_h3, W_l3, prev, out_mask, out_cm);
    // 7. out = input * curr_m[..., None]
    mul_kernel<<<(ROWS * (C / 4)) / 256, 256>>>(input, out);
}